// round 14
// baseline (speedup 1.0000x reference)
#include <cuda_runtime.h>
#include <cuda_fp16.h>
#include <cstdint>
#include <math.h>

typedef unsigned int u32;
typedef unsigned long long u64;

#define N 4096
#define KK 4
#define TS 128
#define NBJ (N / TS)
#define NPAIR 496
#define NBLK 528
#define NCTA 296
#define EPSF 1e-6f

// g_part layout: [stat s][colblock cb][row]
__device__ float g_part[9 * NBJ * N];
__device__ float g_bsum[16];
__device__ u32   g_arrive = 0;   // combine ticket, reset by finalizer
__device__ u32   g_tix = 0;      // tile work-steal counter, reset by finalizer
__device__ u32   g_bar[2];       // monotonic barrier counters (never reset)
__device__ int   g_estride;

// Pre-split, pre-swizzled fp16: [row(4096)][256 bytes]
__device__ __align__(256) unsigned char g_xf16[4096 * 256];

__device__ __forceinline__ u32 smem_u32(const void* p) {
    u32 a;
    asm("{ .reg .u64 t; cvta.to.shared.u64 t, %1; cvt.u32.u64 %0, t; }" : "=r"(a) : "l"(p));
    return a;
}

__device__ __forceinline__ void cp_async16(u32 smem_dst, const void* gsrc) {
    asm volatile("cp.async.cg.shared.global [%0], [%1], 16;"
                 :: "r"(smem_dst), "l"(gsrc) : "memory");
}

__device__ __forceinline__ void cp_commit_wait0() {
    asm volatile("cp.async.commit_group;" ::: "memory");
    asm volatile("cp.async.wait_group 0;" ::: "memory");
}

__device__ __forceinline__ void ldsm_x4(u32* r, u32 addr) {
    asm volatile("ldmatrix.sync.aligned.m8n8.x4.shared.b16 {%0,%1,%2,%3}, [%4];"
                 : "=r"(r[0]), "=r"(r[1]), "=r"(r[2]), "=r"(r[3]) : "r"(addr));
}

__device__ __forceinline__ void ldsm_x2(u32* r, u32 addr) {
    asm volatile("ldmatrix.sync.aligned.m8n8.x2.shared.b16 {%0,%1}, [%2];"
                 : "=r"(r[0]), "=r"(r[1]) : "r"(addr));
}

__device__ __forceinline__ void mma_f16(float* c, const u32* a, const u32* b) {
    asm volatile(
        "mma.sync.aligned.m16n8k16.row.col.f32.f16.f16.f32 "
        "{%0,%1,%2,%3}, {%4,%5,%6,%7}, {%8,%9}, {%0,%1,%2,%3};"
        : "+f"(c[0]), "+f"(c[1]), "+f"(c[2]), "+f"(c[3])
        : "r"(a[0]), "r"(a[1]), "r"(a[2]), "r"(a[3]), "r"(b[0]), "r"(b[1]));
}

// Monotonic device-wide barrier: counter only grows; each launch adds exactly
// NCTA, so target = (ticket/NCTA + 1)*NCTA. Safe across graph replays, no reset.
__device__ __forceinline__ void global_barrier(int id) {
    __syncthreads();
    if (threadIdx.x == 0) {
        __threadfence();
        u32 my = atomicAdd(&g_bar[id], 1u);
        u32 target = (my / NCTA + 1u) * NCTA;
        while (*(volatile u32*)&g_bar[id] < target) { }
        __threadfence();
    }
    __syncthreads();
}

// smem: A tile 32KB at 0, B tile 32KB at 32768, misc after
#define OFF_A     0
#define OFF_B     32768
#define OFF_TBL   65536
#define OFF_STI   65792
#define OFF_STJ   66304
#define OFF_LABI  66816
#define OFF_LABJ  68864
#define SMEM_BYTES 70912

#define OFF_SRED1 0
#define OFF_SRED2 20480

// Tile row layout: 128 rows x 256 bytes (128 fp16), 16B blocks XOR-swizzled.
__device__ __forceinline__ int sw_addr(int row, int c16) {
    return row * 256 + ((c16 ^ (row & 7)) << 4);
}

__global__ __launch_bounds__(256, 2) void fused_kernel(
    const float* __restrict__ X,
    const int* __restrict__ labels,
    float a0, float a1, float a2, float a3,
    float* __restrict__ out)
{
    extern __shared__ char smem[];
    const u32 sbase = smem_u32(smem);
    float4* tbl = (float4*)(smem + OFF_TBL);
    int* sTi = (int*)(smem + OFF_STI);
    int* sTj = (int*)(smem + OFF_STJ);
    int4* sLabI = (int4*)(smem + OFF_LABI);
    int4* sLabJ = (int4*)(smem + OFF_LABJ);
    __shared__ u32 sTix;
    __shared__ u32 sTk;

    const int tid = threadIdx.x;
    const int lane = tid & 31;
    const int wid = tid >> 5;
    const int wr = wid >> 2;
    const int wc = wid & 3;

    // ================= phase 1: fp32 -> fp16 split (pre-swizzled) =========
    {
        int idx = blockIdx.x * 256 + tid;   // 0..75775, work 0..65535
        if (idx < 65536) {
            int row = idx >> 4;
            int c16 = idx & 15;
            const float4* Xg = (const float4*)X;
            float4 v0 = Xg[row * 32 + c16 * 2];
            float4 v1 = Xg[row * 32 + c16 * 2 + 1];
            float vv[8];
            vv[0] = v0.x; vv[1] = v0.y; vv[2] = v0.z; vv[3] = v0.w;
            vv[4] = v1.x; vv[5] = v1.y; vv[6] = v1.z; vv[7] = v1.w;
            u32 hw[8];
            #pragma unroll
            for (int e = 0; e < 8; e++) {
                hw[e] = (u32)__half_as_ushort(__float2half_rn(vv[e]));
            }
            uint4 hv;
            hv.x = hw[0] | (hw[1] << 16);
            hv.y = hw[2] | (hw[3] << 16);
            hv.z = hw[4] | (hw[5] << 16);
            hv.w = hw[6] | (hw[7] << 16);
            u64 off = ((u64)row << 8) + (u64)(((c16 ^ (row & 7))) << 4);
            *(uint4*)(g_xf16 + off) = hv;
        }
        if (blockIdx.x == 0 && tid < 32) {
            int lv2 = 0;
            if (tid < 16) lv2 = labels[2 * tid + 1];
            u32 m = __ballot_sync(0xffffffffu, lv2 != 0);
            if (tid == 0) g_estride = (m != 0) ? 1 : 2;
        }
    }

    global_barrier(0);
    const int es = g_estride;

    // neg-pattern table (persistent in smem above the tile buffers)
    if (tid < 16) {
        int eb = tid;
        int e0 = eb & 1;
        int e1 = (eb >> 1) & 1;
        int e2 = (eb >> 2) & 1;
        int e3 = (eb >> 3) & 1;
        int n0 = 1 - e3;
        int n1 = (1 - e2) & e3;
        int n2 = (1 - e1) & e2;
        int n3 = (1 - e0) & e1;
        float kcnt = (float)(n0 + n1 + n2 + n3);
        float sa = n0 * a0 + n1 * a1 + n2 * a2 + n3 * a3;
        float sa2 = n0 * a0 * a0 + n1 * a1 * a1 + n2 * a2 * a2 + n3 * a3 * a3;
        tbl[eb] = make_float4(kcnt, sa, sa2, 0.0f);
    }

    // ================= phase 2: work-stealing tile loop ====================
    const int a_row = lane & 15;
    const int a_k = lane >> 4;
    const int b_row = lane & 7;
    const int b_k = (lane >> 3) & 1;

    for (;;) {
        __syncthreads();   // previous tile's smem readers done; tbl visible
        if (tid == 0) sTix = atomicAdd(&g_tix, 1u);
        __syncthreads();
        u32 t = sTix;
        if (t >= NBLK) break;

        int bi;
        int bj;
        if (t < NPAIR) {
            int rem = (int)t;
            bi = 0;
            while (rem >= 31 - bi) {
                rem -= 31 - bi;
                bi++;
            }
            bj = bi + 1 + rem;
        } else {
            bi = (int)t - NPAIR;
            bj = bi;
        }
        const int isdiag = (bi == bj) ? 1 : 0;
        const int ibase = bi * TS;
        const int jbase = bj * TS;

        // bulk-copy both pre-swizzled fp16 tiles
        {
            const unsigned char* srcA = g_xf16 + ((u64)ibase << 8);
            const unsigned char* srcB = g_xf16 + ((u64)jbase << 8);
            #pragma unroll
            for (int p = 0; p < 8; p++) {
                int woff = (p * 256 + tid) << 4;
                cp_async16(sbase + OFF_A + woff, srcA + woff);
                cp_async16(sbase + OFF_B + woff, srcB + woff);
            }
        }

        // labels for both blocks (overlaps cp.async)
        if (tid < 128) {
            int gi = ibase + tid;
            sTi[tid] = labels[(gi * KK) * es];
            int4 lv4;
            lv4.x = labels[(gi * KK + 0) * es];
            lv4.y = labels[(gi * KK + 1) * es];
            lv4.z = labels[(gi * KK + 2) * es];
            lv4.w = labels[(gi * KK + 3) * es];
            sLabI[tid] = lv4;
        } else {
            int r = tid - 128;
            int gj = jbase + r;
            sTj[r] = labels[(gj * KK) * es];
            int4 lv4;
            lv4.x = labels[(gj * KK + 0) * es];
            lv4.y = labels[(gj * KK + 1) * es];
            lv4.z = labels[(gj * KK + 2) * es];
            lv4.w = labels[(gj * KK + 3) * es];
            sLabJ[r] = lv4;
        }

        float acc[4][4][4];
        #pragma unroll
        for (int mt = 0; mt < 4; mt++)
            #pragma unroll
            for (int nt = 0; nt < 4; nt++)
                #pragma unroll
                for (int q = 0; q < 4; q++)
                    acc[mt][nt][q] = 0.0f;

        cp_commit_wait0();
        __syncthreads();

        // fp16 GEMM: 8 k-steps x 16 mma
        #pragma unroll
        for (int ks = 0; ks < 8; ks++) {
            u32 bh[4][2];
            int c16b = ks * 2 + b_k;
            #pragma unroll
            for (int nt = 0; nt < 4; nt++) {
                int r = wc * 32 + nt * 8 + b_row;
                ldsm_x2(bh[nt], sbase + OFF_B + (u32)sw_addr(r, c16b));
            }
            int c16a = ks * 2 + a_k;
            #pragma unroll
            for (int mt = 0; mt < 4; mt++) {
                int r = wr * 64 + mt * 16 + a_row;
                u32 ah[4];
                ldsm_x4(ah, sbase + OFF_A + (u32)sw_addr(r, c16a));
                #pragma unroll
                for (int nt = 0; nt < 4; nt++) {
                    mma_f16(acc[mt][nt], ah, bh[nt]);
                }
            }
        }

        __syncthreads();   // tile smem now free for reduce scratch

        // acc -> log in place
        #pragma unroll
        for (int mt = 0; mt < 4; mt++)
            #pragma unroll
            for (int nt = 0; nt < 4; nt++)
                #pragma unroll
                for (int q = 0; q < 4; q++)
                    acc[mt][nt][q] = __logf(acc[mt][nt][q] + EPSF);

        float* sred1 = (float*)(smem + OFF_SRED1);
        float* sred2 = (float*)(smem + OFF_SRED2);

        // orientation 1: i-block rows over j-block cols
        #pragma unroll
        for (int mt = 0; mt < 4; mt++) {
            #pragma unroll
            for (int h = 0; h < 2; h++) {
                int row = wr * 64 + mt * 16 + (lane >> 2) + h * 8;
                int tlab = sTi[row];
                int selfcol = (isdiag != 0) ? row : -1;
                float st[9];
                #pragma unroll
                for (int s = 0; s < 9; s++) st[s] = 0.0f;
                #pragma unroll
                for (int nt = 0; nt < 4; nt++) {
                    #pragma unroll
                    for (int e = 0; e < 2; e++) {
                        float L = acc[mt][nt][h * 2 + e];
                        float L2 = L * L;
                        int col = wc * 32 + nt * 8 + ((lane & 3) << 1) + e;
                        int4 lbv = sLabJ[col];
                        int p0 = (tlab == lbv.x) ? 1 : 0;
                        int eb = p0 | (((tlab == lbv.y) ? 1 : 0) << 1) |
                                 (((tlab == lbv.z) ? 1 : 0) << 2) |
                                 (((tlab == lbv.w) ? 1 : 0) << 3);
                        float4 tv = tbl[eb];
                        st[3] += tv.x;
                        st[4] += tv.y;
                        st[5] += tv.z;
                        st[6] = fmaf(tv.x, L, st[6]);
                        st[7] = fmaf(tv.y, L, st[7]);
                        st[8] = fmaf(tv.x, L2, st[8]);
                        if ((p0 != 0) && (col != selfcol)) {
                            st[0] += 1.0f;
                            st[1] += L;
                            st[2] += L2;
                        }
                    }
                }
                #pragma unroll
                for (int s = 0; s < 9; s++) {
                    float v = st[s];
                    v += __shfl_xor_sync(0xffffffffu, v, 1);
                    v += __shfl_xor_sync(0xffffffffu, v, 2);
                    st[s] = v;
                }
                if ((lane & 3) == 0) {
                    #pragma unroll
                    for (int s = 0; s < 9; s++) sred1[(row * 4 + wc) * 9 + s] = st[s];
                }
            }
        }

        // orientation 2 (off-diag only): j-block rows over i-block cols
        if (isdiag == 0) {
            #pragma unroll
            for (int nt = 0; nt < 4; nt++) {
                #pragma unroll
                for (int e = 0; e < 2; e++) {
                    int col = wc * 32 + nt * 8 + ((lane & 3) << 1) + e;
                    int tlab2 = sTj[col];
                    float st[9];
                    #pragma unroll
                    for (int s = 0; s < 9; s++) st[s] = 0.0f;
                    #pragma unroll
                    for (int mt = 0; mt < 4; mt++) {
                        #pragma unroll
                        for (int h = 0; h < 2; h++) {
                            float L = acc[mt][nt][h * 2 + e];
                            float L2 = L * L;
                            int row = wr * 64 + mt * 16 + (lane >> 2) + h * 8;
                            int4 lbv = sLabI[row];
                            int p0 = (tlab2 == lbv.x) ? 1 : 0;
                            int eb = p0 | (((tlab2 == lbv.y) ? 1 : 0) << 1) |
                                     (((tlab2 == lbv.z) ? 1 : 0) << 2) |
                                     (((tlab2 == lbv.w) ? 1 : 0) << 3);
                            float4 tv = tbl[eb];
                            st[3] += tv.x;
                            st[4] += tv.y;
                            st[5] += tv.z;
                            st[6] = fmaf(tv.x, L, st[6]);
                            st[7] = fmaf(tv.y, L, st[7]);
                            st[8] = fmaf(tv.x, L2, st[8]);
                            if (p0 != 0) {
                                st[0] += 1.0f;
                                st[1] += L;
                                st[2] += L2;
                            }
                        }
                    }
                    #pragma unroll
                    for (int s = 0; s < 9; s++) {
                        float v = st[s];
                        v += __shfl_xor_sync(0xffffffffu, v, 4);
                        v += __shfl_xor_sync(0xffffffffu, v, 8);
                        v += __shfl_xor_sync(0xffffffffu, v, 16);
                        st[s] = v;
                    }
                    if ((lane >> 2) == 0) {
                        #pragma unroll
                        for (int s = 0; s < 9; s++) sred2[(col * 2 + wr) * 9 + s] = st[s];
                    }
                }
            }
        }
        __syncthreads();

        // write-once g_part [s][cb][row] (coalesced)
        if (tid < 128) {
            #pragma unroll
            for (int s = 0; s < 9; s++) {
                float v = sred1[(tid * 4 + 0) * 9 + s] + sred1[(tid * 4 + 1) * 9 + s] +
                          sred1[(tid * 4 + 2) * 9 + s] + sred1[(tid * 4 + 3) * 9 + s];
                g_part[(s * NBJ + bj) * N + ibase + tid] = v;
            }
        } else if (isdiag == 0) {
            int c2 = tid - 128;
            #pragma unroll
            for (int s = 0; s < 9; s++) {
                float v = sred2[(c2 * 2 + 0) * 9 + s] + sred2[(c2 * 2 + 1) * 9 + s];
                g_part[(s * NBJ + bi) * N + jbase + c2] = v;
            }
        }
    }

    global_barrier(1);

    // ================= phase 3: combine (first 16 CTAs) ====================
    if (blockIdx.x < 16) {
        const int row = blockIdx.x * 256 + tid;
        float agg[9];
        #pragma unroll
        for (int s = 0; s < 9; s++) {
            float v = 0.0f;
            #pragma unroll
            for (int cb = 0; cb < NBJ; cb++) {
                v += g_part[(s * NBJ + cb) * N + row];
            }
            agg[s] = v;
        }
        float rl = agg[2] * agg[3] - 2.0f * agg[1] * (agg[6] + agg[4])
                 + agg[0] * (agg[8] + 2.0f * agg[7] + agg[5]);
        float* sh = (float*)smem;
        sh[tid] = rl;
        __syncthreads();
        for (int o = 128; o > 0; o >>= 1) {
            if (tid < o) sh[tid] += sh[tid + o];
            __syncthreads();
        }
        if (tid == 0) {
            g_bsum[blockIdx.x] = sh[0];
            __threadfence();
            sTk = atomicAdd(&g_arrive, 1u);
        }
        __syncthreads();
        if (sTk == 15u && tid == 0) {
            __threadfence();
            float ssum = 0.0f;
            #pragma unroll
            for (int b = 0; b < 16; b++) ssum += g_bsum[b];
            out[0] = ssum;
            g_arrive = 0;   // safe: all CTAs past barrier 1, none read these again
            g_tix = 0;
        }
    }
}

extern "C" void kernel_launch(void* const* d_in, const int* in_sizes, int n_in,
                              void* d_out, int out_size) {
    (void)in_sizes; (void)n_in; (void)out_size;
    const float* X = (const float*)d_in[0];
    const int* labels = (const int*)d_in[1];
    float* out = (float*)d_out;

    const double lg = log(0.1 + 1e-6);
    float a[4];
    for (int m = 0; m < 4; m++) {
        a[m] = (float)(0.1 * (lg - log(pow(0.1, (double)(5 - m)) + 1e-6)));
    }

    cudaFuncSetAttribute(fused_kernel, cudaFuncAttributeMaxDynamicSharedMemorySize, SMEM_BYTES);

    fused_kernel<<<NCTA, 256, SMEM_BYTES>>>(X, labels, a[0], a[1], a[2], a[3], out);
}

// round 15
// speedup vs baseline: 1.4134x; 1.4134x over previous
#include <cuda_runtime.h>
#include <cuda_fp16.h>
#include <cstdint>
#include <math.h>

typedef unsigned int u32;
typedef unsigned long long u64;

#define N 4096
#define KK 4
#define TS 128
#define NBJ (N / TS)
#define NPAIR 496
#define NBLK 528
#define NCTA 296
#define EPSF 1e-6f

// g_part layout: [stat s(5)][colblock cb][row]; stats: 0=S1 1=S2 2=U1 3=UA 4=U2
__device__ float g_part[5 * NBJ * N];
__device__ float4 g_ntab[64];        // per target value: (NA, NB, NC, hist)
__device__ u32   g_labcat[N];        // packed 4x8bit labels per row
__device__ float g_bsum[16];
__device__ u32   g_arrive = 0;
__device__ u32   g_tix = 0;
__device__ u32   g_bar[2];           // monotonic barrier counters
// Pre-swizzled fp16 X: [row(4096)][256 bytes]
__device__ __align__(256) unsigned char g_xf16[4096 * 256];

__device__ __forceinline__ u32 smem_u32(const void* p) {
    u32 a;
    asm("{ .reg .u64 t; cvta.to.shared.u64 t, %1; cvt.u32.u64 %0, t; }" : "=r"(a) : "l"(p));
    return a;
}

__device__ __forceinline__ void cp_async16(u32 smem_dst, const void* gsrc) {
    asm volatile("cp.async.cg.shared.global [%0], [%1], 16;"
                 :: "r"(smem_dst), "l"(gsrc) : "memory");
}

__device__ __forceinline__ void cp_commit_wait0() {
    asm volatile("cp.async.commit_group;" ::: "memory");
    asm volatile("cp.async.wait_group 0;" ::: "memory");
}

__device__ __forceinline__ void ldsm_x4(u32* r, u32 addr) {
    asm volatile("ldmatrix.sync.aligned.m8n8.x4.shared.b16 {%0,%1,%2,%3}, [%4];"
                 : "=r"(r[0]), "=r"(r[1]), "=r"(r[2]), "=r"(r[3]) : "r"(addr));
}

__device__ __forceinline__ void ldsm_x2(u32* r, u32 addr) {
    asm volatile("ldmatrix.sync.aligned.m8n8.x2.shared.b16 {%0,%1}, [%2];"
                 : "=r"(r[0]), "=r"(r[1]) : "r"(addr));
}

__device__ __forceinline__ void mma_f16(float* c, const u32* a, const u32* b) {
    asm volatile(
        "mma.sync.aligned.m16n8k16.row.col.f32.f16.f16.f32 "
        "{%0,%1,%2,%3}, {%4,%5,%6,%7}, {%8,%9}, {%0,%1,%2,%3};"
        : "+f"(c[0]), "+f"(c[1]), "+f"(c[2]), "+f"(c[3])
        : "r"(a[0]), "r"(a[1]), "r"(a[2]), "r"(a[3]), "r"(b[0]), "r"(b[1]));
}

__device__ __forceinline__ void global_barrier(int id) {
    __syncthreads();
    if (threadIdx.x == 0) {
        __threadfence();
        u32 my = atomicAdd(&g_bar[id], 1u);
        u32 target = (my / NCTA + 1u) * NCTA;
        while (*(volatile u32*)&g_bar[id] < target) { }
        __threadfence();
    }
    __syncthreads();
}

// eb from packed labels vs replicated target byte: zero-byte detect + dp4a.
__device__ __forceinline__ void eb_calc(u32 lc, u32 tcat, u32& zz, int& eb) {
    u32 d = lc ^ tcat;
    u32 z = (d - 0x01010101u) & ~d & 0x80808080u;
    zz = z >> 7;                       // bytes 0/1 at equal positions
    eb = (int)__dp4a(zz, 0x08040201u, 0u);
}

// smem: A 32KB @0, B 32KB @32768, tbl4 @65536, tbl2 @65792, labCI @65920, labCJ @66432
#define OFF_A     0
#define OFF_B     32768
#define OFF_TBL4  65536
#define OFF_TBL2  65792
#define OFF_LCI   65920
#define OFF_LCJ   66432
#define SMEM_BYTES 70912

#define OFF_SRED1 0        // 128 rows x 4 wc x 5 stats = 10KB
#define OFF_SRED2 20480    // 128 cols x 2 wr x 5 stats = 5KB

__device__ __forceinline__ int sw_addr(int row, int c16) {
    return row * 256 + ((c16 ^ (row & 7)) << 4);
}

__global__ __launch_bounds__(256, 2) void fused_kernel(
    const float* __restrict__ X,
    const int* __restrict__ labels,
    float a0, float a1, float a2, float a3,
    float* __restrict__ out)
{
    extern __shared__ char smem[];
    const u32 sbase = smem_u32(smem);
    float4* tbl4 = (float4*)(smem + OFF_TBL4);
    float2* tbl2 = (float2*)(smem + OFF_TBL2);
    u32* sLabCI = (u32*)(smem + OFF_LCI);
    u32* sLabCJ = (u32*)(smem + OFF_LCJ);
    __shared__ u32 sTix;
    __shared__ u32 sTk;
    __shared__ int sES;

    const int tid = threadIdx.x;
    const int lane = tid & 31;
    const int wid = tid >> 5;
    const int wr = wid >> 2;
    const int wc = wid & 3;

    // per-CTA labels layout detection (no cross-CTA dependency)
    if (wid == 0) {
        int lv2 = 0;
        if (lane < 16) lv2 = labels[2 * lane + 1];
        u32 m = __ballot_sync(0xffffffffu, lv2 != 0);
        if (lane == 0) sES = (m != 0) ? 1 : 2;
    }
    // pattern tables (persistent)
    if (tid >= 32 && tid < 48) {
        int eb = tid - 32;
        int e0 = eb & 1;
        int e1 = (eb >> 1) & 1;
        int e2 = (eb >> 2) & 1;
        int e3 = (eb >> 3) & 1;
        int n0 = 1 - e3;
        int n1 = (1 - e2) & e3;
        int n2 = (1 - e1) & e2;
        int n3 = (1 - e0) & e1;
        float kcnt = (float)(n0 + n1 + n2 + n3);
        float sa = n0 * a0 + n1 * a1 + n2 * a2 + n3 * a3;
        float sa2 = n0 * a0 * a0 + n1 * a1 * a1 + n2 * a2 * a2 + n3 * a3 * a3;
        tbl4[eb] = make_float4(kcnt, sa, sa2, 0.0f);
        tbl2[eb] = make_float2(kcnt, sa);
    }
    __syncthreads();
    const int es = sES;

    // ============ phase 1: split X to fp16 (pre-swizzled) + labcat =========
    {
        int idx = blockIdx.x * 256 + tid;
        if (idx < 65536) {
            int row = idx >> 4;
            int c16 = idx & 15;
            const float4* Xg = (const float4*)X;
            float4 v0 = Xg[row * 32 + c16 * 2];
            float4 v1 = Xg[row * 32 + c16 * 2 + 1];
            float vv[8];
            vv[0] = v0.x; vv[1] = v0.y; vv[2] = v0.z; vv[3] = v0.w;
            vv[4] = v1.x; vv[5] = v1.y; vv[6] = v1.z; vv[7] = v1.w;
            u32 hw[8];
            #pragma unroll
            for (int e = 0; e < 8; e++) {
                hw[e] = (u32)__half_as_ushort(__float2half_rn(vv[e]));
            }
            uint4 hv;
            hv.x = hw[0] | (hw[1] << 16);
            hv.y = hw[2] | (hw[3] << 16);
            hv.z = hw[4] | (hw[5] << 16);
            hv.w = hw[6] | (hw[7] << 16);
            u64 off = ((u64)row << 8) + (u64)(((c16 ^ (row & 7))) << 4);
            *(uint4*)(g_xf16 + off) = hv;
        }
        if (blockIdx.x < 16) {
            int j = blockIdx.x * 256 + tid;
            u32 l0 = (u32)labels[(j * KK + 0) * es];
            u32 l1 = (u32)labels[(j * KK + 1) * es];
            u32 l2 = (u32)labels[(j * KK + 2) * es];
            u32 l3 = (u32)labels[(j * KK + 3) * es];
            g_labcat[j] = l0 | (l1 << 8) | (l2 << 16) | (l3 << 24);
        }
    }

    global_barrier(0);

    // ============ phase 1.5: CTAs 0..63 build g_ntab[t] ====================
    if (blockIdx.x < 64) {
        u32 t = (u32)blockIdx.x;
        u32 tcat = t * 0x01010101u;
        float na = 0.0f;
        float nb = 0.0f;
        float nc = 0.0f;
        float cnt = 0.0f;
        #pragma unroll
        for (int q = 0; q < 16; q++) {
            u32 lc = g_labcat[q * 256 + tid];
            u32 zz;
            int eb;
            eb_calc(lc, tcat, zz, eb);
            float4 tv = tbl4[eb];
            na += tv.x;
            nb += tv.y;
            nc += tv.z;
            cnt += (float)(zz & 1u);
        }
        float4* sh4 = (float4*)smem;   // OFF_A region, pre-tile
        sh4[tid] = make_float4(na, nb, nc, cnt);
        __syncthreads();
        for (int o = 128; o > 0; o >>= 1) {
            if (tid < o) {
                float4 a4 = sh4[tid];
                float4 b4 = sh4[tid + o];
                sh4[tid] = make_float4(a4.x + b4.x, a4.y + b4.y, a4.z + b4.z, a4.w + b4.w);
            }
            __syncthreads();
        }
        if (tid == 0) g_ntab[t] = sh4[0];
        __syncthreads();
    }

    // ============ phase 2: work-stealing tile loop =========================
    const int a_row = lane & 15;
    const int a_k = lane >> 4;
    const int b_row = lane & 7;
    const int b_k = (lane >> 3) & 1;

    for (;;) {
        __syncthreads();
        if (tid == 0) sTix = atomicAdd(&g_tix, 1u);
        __syncthreads();
        u32 t = sTix;
        if (t >= NBLK) break;

        int bi;
        int bj;
        if (t < NPAIR) {
            int rem = (int)t;
            bi = 0;
            while (rem >= 31 - bi) {
                rem -= 31 - bi;
                bi++;
            }
            bj = bi + 1 + rem;
        } else {
            bi = (int)t - NPAIR;
            bj = bi;
        }
        const int isdiag = (bi == bj) ? 1 : 0;
        const int ibase = bi * TS;
        const int jbase = bj * TS;

        // bulk-copy fp16 tiles
        {
            const unsigned char* srcA = g_xf16 + ((u64)ibase << 8);
            const unsigned char* srcB = g_xf16 + ((u64)jbase << 8);
            #pragma unroll
            for (int p = 0; p < 8; p++) {
                int woff = (p * 256 + tid) << 4;
                cp_async16(sbase + OFF_A + woff, srcA + woff);
                cp_async16(sbase + OFF_B + woff, srcB + woff);
            }
        }
        // packed labels into smem (overlaps cp.async)
        if (tid < 32) {
            ((uint4*)sLabCI)[tid] = ((const uint4*)(g_labcat + ibase))[tid];
        } else if (tid < 64) {
            ((uint4*)sLabCJ)[tid - 32] = ((const uint4*)(g_labcat + jbase))[tid - 32];
        }

        float acc[4][4][4];
        #pragma unroll
        for (int mt = 0; mt < 4; mt++)
            #pragma unroll
            for (int nt = 0; nt < 4; nt++)
                #pragma unroll
                for (int q = 0; q < 4; q++)
                    acc[mt][nt][q] = 0.0f;

        cp_commit_wait0();
        __syncthreads();

        // fp16 GEMM: 8 k-steps x 16 mma
        #pragma unroll
        for (int ks = 0; ks < 8; ks++) {
            u32 bh[4][2];
            int c16b = ks * 2 + b_k;
            #pragma unroll
            for (int nt = 0; nt < 4; nt++) {
                int r = wc * 32 + nt * 8 + b_row;
                ldsm_x2(bh[nt], sbase + OFF_B + (u32)sw_addr(r, c16b));
            }
            int c16a = ks * 2 + a_k;
            #pragma unroll
            for (int mt = 0; mt < 4; mt++) {
                int r = wr * 64 + mt * 16 + a_row;
                u32 ah[4];
                ldsm_x4(ah, sbase + OFF_A + (u32)sw_addr(r, c16a));
                #pragma unroll
                for (int nt = 0; nt < 4; nt++) {
                    mma_f16(acc[mt][nt], ah, bh[nt]);
                }
            }
        }

        __syncthreads();   // tile smem free for sred

        // acc -> log in place
        #pragma unroll
        for (int mt = 0; mt < 4; mt++)
            #pragma unroll
            for (int nt = 0; nt < 4; nt++)
                #pragma unroll
                for (int q = 0; q < 4; q++)
                    acc[mt][nt][q] = __logf(acc[mt][nt][q] + EPSF);

        float* sred1 = (float*)(smem + OFF_SRED1);
        float* sred2 = (float*)(smem + OFF_SRED2);

        // hoisted packed labels for this thread's 8 cols and 8 rows
        u32 lcJ[8];
        #pragma unroll
        for (int nt = 0; nt < 4; nt++) {
            #pragma unroll
            for (int e = 0; e < 2; e++) {
                lcJ[nt * 2 + e] = sLabCJ[wc * 32 + nt * 8 + ((lane & 3) << 1) + e];
            }
        }
        u32 lcI[8];
        #pragma unroll
        for (int mt = 0; mt < 4; mt++) {
            #pragma unroll
            for (int h = 0; h < 2; h++) {
                lcI[mt * 2 + h] = sLabCI[wr * 64 + mt * 16 + (lane >> 2) + h * 8];
            }
        }

        // ---- orientation 1: i-rows over j-cols; stats S1,S2,U1,UA,U2 ----
        #pragma unroll
        for (int mt = 0; mt < 4; mt++) {
            #pragma unroll
            for (int h = 0; h < 2; h++) {
                int row = wr * 64 + mt * 16 + (lane >> 2) + h * 8;
                u32 tcat = (lcI[mt * 2 + h] & 0xFFu) * 0x01010101u;
                int selfcol = (isdiag != 0) ? row : -1;
                float st[5];
                #pragma unroll
                for (int s = 0; s < 5; s++) st[s] = 0.0f;
                #pragma unroll
                for (int nt = 0; nt < 4; nt++) {
                    #pragma unroll
                    for (int e = 0; e < 2; e++) {
                        float L = acc[mt][nt][h * 2 + e];
                        u32 zz;
                        int eb;
                        eb_calc(lcJ[nt * 2 + e], tcat, zz, eb);
                        float2 tv = tbl2[eb];
                        float kl = tv.x * L;
                        st[2] += kl;                    // U1
                        st[3] = fmaf(tv.y, L, st[3]);   // UA
                        st[4] = fmaf(kl, L, st[4]);     // U2
                        int col = wc * 32 + nt * 8 + ((lane & 3) << 1) + e;
                        if ((zz & 1u) != 0u && col != selfcol) {
                            st[0] += L;                 // S1
                            st[1] = fmaf(L, L, st[1]);  // S2
                        }
                    }
                }
                #pragma unroll
                for (int s = 0; s < 5; s++) {
                    float v = st[s];
                    v += __shfl_xor_sync(0xffffffffu, v, 1);
                    v += __shfl_xor_sync(0xffffffffu, v, 2);
                    st[s] = v;
                }
                if ((lane & 3) == 0) {
                    #pragma unroll
                    for (int s = 0; s < 5; s++) sred1[(row * 4 + wc) * 5 + s] = st[s];
                }
            }
        }

        // ---- orientation 2 (off-diag): j-rows over i-cols ----
        if (isdiag == 0) {
            #pragma unroll
            for (int nt = 0; nt < 4; nt++) {
                #pragma unroll
                for (int e = 0; e < 2; e++) {
                    int col = wc * 32 + nt * 8 + ((lane & 3) << 1) + e;
                    u32 tcat2 = (lcJ[nt * 2 + e] & 0xFFu) * 0x01010101u;
                    float st[5];
                    #pragma unroll
                    for (int s = 0; s < 5; s++) st[s] = 0.0f;
                    #pragma unroll
                    for (int mt = 0; mt < 4; mt++) {
                        #pragma unroll
                        for (int h = 0; h < 2; h++) {
                            float L = acc[mt][nt][h * 2 + e];
                            u32 zz;
                            int eb;
                            eb_calc(lcI[mt * 2 + h], tcat2, zz, eb);
                            float2 tv = tbl2[eb];
                            float kl = tv.x * L;
                            st[2] += kl;
                            st[3] = fmaf(tv.y, L, st[3]);
                            st[4] = fmaf(kl, L, st[4]);
                            if ((zz & 1u) != 0u) {
                                st[0] += L;
                                st[1] = fmaf(L, L, st[1]);
                            }
                        }
                    }
                    #pragma unroll
                    for (int s = 0; s < 5; s++) {
                        float v = st[s];
                        v += __shfl_xor_sync(0xffffffffu, v, 4);
                        v += __shfl_xor_sync(0xffffffffu, v, 8);
                        v += __shfl_xor_sync(0xffffffffu, v, 16);
                        st[s] = v;
                    }
                    if ((lane >> 2) == 0) {
                        #pragma unroll
                        for (int s = 0; s < 5; s++) sred2[(col * 2 + wr) * 5 + s] = st[s];
                    }
                }
            }
        }
        __syncthreads();

        // write-once g_part [s][cb][row] (coalesced)
        if (tid < 128) {
            #pragma unroll
            for (int s = 0; s < 5; s++) {
                float v = sred1[(tid * 4 + 0) * 5 + s] + sred1[(tid * 4 + 1) * 5 + s] +
                          sred1[(tid * 4 + 2) * 5 + s] + sred1[(tid * 4 + 3) * 5 + s];
                g_part[(s * NBJ + bj) * N + ibase + tid] = v;
            }
        } else if (isdiag == 0) {
            int c2 = tid - 128;
            #pragma unroll
            for (int s = 0; s < 5; s++) {
                float v = sred2[(c2 * 2 + 0) * 5 + s] + sred2[(c2 * 2 + 1) * 5 + s];
                g_part[(s * NBJ + bi) * N + jbase + c2] = v;
            }
        }
    }

    global_barrier(1);

    // ============ phase 3: combine (first 16 CTAs) =========================
    if (blockIdx.x < 16) {
        const int row = blockIdx.x * 256 + tid;
        float agg[5];
        #pragma unroll
        for (int s = 0; s < 5; s++) {
            float v = 0.0f;
            #pragma unroll
            for (int cb = 0; cb < NBJ; cb++) {
                v += g_part[(s * NBJ + cb) * N + row];
            }
            agg[s] = v;
        }
        float4 ntb = g_ntab[g_labcat[row] & 0xFFu];
        float cpos = ntb.w - 1.0f;
        float rl = agg[1] * ntb.x - 2.0f * agg[0] * (agg[2] + ntb.y)
                 + cpos * (agg[4] + 2.0f * agg[3] + ntb.z);
        float* sh = (float*)smem;
        sh[tid] = rl;
        __syncthreads();
        for (int o = 128; o > 0; o >>= 1) {
            if (tid < o) sh[tid] += sh[tid + o];
            __syncthreads();
        }
        if (tid == 0) {
            g_bsum[blockIdx.x] = sh[0];
            __threadfence();
            sTk = atomicAdd(&g_arrive, 1u);
        }
        __syncthreads();
        if (sTk == 15u && tid == 0) {
            __threadfence();
            float ssum = 0.0f;
            #pragma unroll
            for (int b = 0; b < 16; b++) ssum += g_bsum[b];
            out[0] = ssum;
            g_arrive = 0;
            g_tix = 0;
        }
    }
}

extern "C" void kernel_launch(void* const* d_in, const int* in_sizes, int n_in,
                              void* d_out, int out_size) {
    (void)in_sizes; (void)n_in; (void)out_size;
    const float* X = (const float*)d_in[0];
    const int* labels = (const int*)d_in[1];
    float* out = (float*)d_out;

    const double lg = log(0.1 + 1e-6);
    float a[4];
    for (int m = 0; m < 4; m++) {
        a[m] = (float)(0.1 * (lg - log(pow(0.1, (double)(5 - m)) + 1e-6)));
    }

    cudaFuncSetAttribute(fused_kernel, cudaFuncAttributeMaxDynamicSharedMemorySize, SMEM_BYTES);

    fused_kernel<<<NCTA, 256, SMEM_BYTES>>>(X, labels, a[0], a[1], a[2], a[3], out);
}